// round 1
// baseline (speedup 1.0000x reference)
#include <cuda_runtime.h>

#define BATCH 32
#define DIM 1024
#define MLEN 512
#define TK 16
#define NKC (MLEN / TK)        /* 32 k-chunks */
#define NTILE 8                /* DIM / 128   */
#define NTRI 36                /* upper-tri tile count */
#define TRIU_PER_B 524800      /* 1024*1025/2 */
#define INV2M (1.0f / 1024.0f)
#define ALPHA_C 0.4f
#define EPS_C 1e-5f

// Scratch (no device allocation allowed)
__device__ float g_diag[BATCH * DIM];
__device__ float g_rowsum[BATCH * DIM];
__device__ float g_rmean[BATCH * DIM];
__device__ float g_tot[BATCH];

// ---------------------------------------------------------------------------
// Kernel 1: diag[b,i] = sum_m x[b,i,m]^2 / (2M); also zero rowsum.
// One warp per row. grid = 32768/8 blocks of 256.
// ---------------------------------------------------------------------------
__global__ void k_diag(const float* __restrict__ x) {
    int row  = blockIdx.x * (blockDim.x >> 5) + (threadIdx.x >> 5);
    int lane = threadIdx.x & 31;
    const float4* p = (const float4*)(x + (size_t)row * MLEN);
    float s = 0.f;
#pragma unroll
    for (int k = 0; k < 4; ++k) {
        float4 v = p[lane + 32 * k];
        s += v.x * v.x + v.y * v.y + v.z * v.z + v.w * v.w;
    }
#pragma unroll
    for (int o = 16; o; o >>= 1) s += __shfl_xor_sync(0xffffffffu, s, o);
    if (lane == 0) {
        g_diag[row]   = s * INV2M;
        g_rowsum[row] = 0.f;
    }
}

// ---------------------------------------------------------------------------
// Kernel 2: fused triu-tiled SGEMM + dcov + pow + packed store + rowsum acc.
// Tile 128x128, K-chunk 16, 256 threads, 8x8 microtile per thread.
// Thread (tx,ty): rows i = ti*128 + ty*8 + ii (consecutive),
//                 cols j = tj*128 + tx + 16*jj (lane-strided -> coalesced STG).
// ---------------------------------------------------------------------------
__global__ void __launch_bounds__(256) k_main(const float* __restrict__ x,
                                              float* __restrict__ out) {
    int blk = blockIdx.x;
    int b   = blk / NTRI;
    int t   = blk - b * NTRI;
    int ti  = 0;
    while (t >= NTILE - ti) { t -= NTILE - ti; ++ti; }
    int tj = ti + t;   // tj >= ti

    __shared__ float As[2][TK][128];
    __shared__ float Bs[2][TK][128];
    __shared__ float cAcc[128];

    int tid = threadIdx.x;
    int tx  = tid & 15;
    int ty  = tid >> 4;

    const float* Abase = x + ((size_t)b * DIM + (size_t)ti * 128) * MLEN;
    const float* Bbase = x + ((size_t)b * DIM + (size_t)tj * 128) * MLEN;

    // staging: thread loads rows (lr, lr+64), 4 consecutive k's at col lc
    int lr = tid >> 2;
    int lc = (tid & 3) * 4;

    float4 pa0, pa1, pb0, pb1;

    float acc[8][8];
#pragma unroll
    for (int i = 0; i < 8; ++i)
#pragma unroll
        for (int j = 0; j < 8; ++j) acc[i][j] = 0.f;

    if (tid < 128) cAcc[tid] = 0.f;

    // prologue: chunk 0
    {
        int k0 = lc;
        pa0 = *(const float4*)(Abase + (size_t)lr * MLEN + k0);
        pa1 = *(const float4*)(Abase + (size_t)(lr + 64) * MLEN + k0);
        pb0 = *(const float4*)(Bbase + (size_t)lr * MLEN + k0);
        pb1 = *(const float4*)(Bbase + (size_t)(lr + 64) * MLEN + k0);
        As[0][lc + 0][lr] = pa0.x; As[0][lc + 1][lr] = pa0.y;
        As[0][lc + 2][lr] = pa0.z; As[0][lc + 3][lr] = pa0.w;
        As[0][lc + 0][lr + 64] = pa1.x; As[0][lc + 1][lr + 64] = pa1.y;
        As[0][lc + 2][lr + 64] = pa1.z; As[0][lc + 3][lr + 64] = pa1.w;
        Bs[0][lc + 0][lr] = pb0.x; Bs[0][lc + 1][lr] = pb0.y;
        Bs[0][lc + 2][lr] = pb0.z; Bs[0][lc + 3][lr] = pb0.w;
        Bs[0][lc + 0][lr + 64] = pb1.x; Bs[0][lc + 1][lr + 64] = pb1.y;
        Bs[0][lc + 2][lr + 64] = pb1.z; Bs[0][lc + 3][lr + 64] = pb1.w;
    }
    __syncthreads();

#pragma unroll 1
    for (int kc = 0; kc < NKC; ++kc) {
        int cur = kc & 1;
        if (kc + 1 < NKC) {
            int k0 = (kc + 1) * TK + lc;
            pa0 = *(const float4*)(Abase + (size_t)lr * MLEN + k0);
            pa1 = *(const float4*)(Abase + (size_t)(lr + 64) * MLEN + k0);
            pb0 = *(const float4*)(Bbase + (size_t)lr * MLEN + k0);
            pb1 = *(const float4*)(Bbase + (size_t)(lr + 64) * MLEN + k0);
        }
#pragma unroll
        for (int k = 0; k < TK; ++k) {
            float4 a0 = *(const float4*)&As[cur][k][ty * 8];
            float4 a1 = *(const float4*)&As[cur][k][ty * 8 + 4];
            float ar[8] = {a0.x, a0.y, a0.z, a0.w, a1.x, a1.y, a1.z, a1.w};
            float br[8];
#pragma unroll
            for (int jj = 0; jj < 8; ++jj) br[jj] = Bs[cur][k][tx + 16 * jj];
#pragma unroll
            for (int ii = 0; ii < 8; ++ii)
#pragma unroll
                for (int jj = 0; jj < 8; ++jj)
                    acc[ii][jj] = fmaf(ar[ii], br[jj], acc[ii][jj]);
        }
        if (kc + 1 < NKC) {
            int nxt = 1 - cur;
            As[nxt][lc + 0][lr] = pa0.x; As[nxt][lc + 1][lr] = pa0.y;
            As[nxt][lc + 2][lr] = pa0.z; As[nxt][lc + 3][lr] = pa0.w;
            As[nxt][lc + 0][lr + 64] = pa1.x; As[nxt][lc + 1][lr + 64] = pa1.y;
            As[nxt][lc + 2][lr + 64] = pa1.z; As[nxt][lc + 3][lr + 64] = pa1.w;
            Bs[nxt][lc + 0][lr] = pb0.x; Bs[nxt][lc + 1][lr] = pb0.y;
            Bs[nxt][lc + 2][lr] = pb0.z; Bs[nxt][lc + 3][lr] = pb0.w;
            Bs[nxt][lc + 0][lr + 64] = pb1.x; Bs[nxt][lc + 1][lr + 64] = pb1.y;
            Bs[nxt][lc + 2][lr + 64] = pb1.z; Bs[nxt][lc + 3][lr + 64] = pb1.w;
            __syncthreads();
        }
    }

    // ---------------- epilogue: dcov -> pow -> store + rowsum partials ------
    int gib = ti * 128 + ty * 8;
    int gjb = tj * 128 + tx;
    float di[8], dj[8];
#pragma unroll
    for (int ii = 0; ii < 8; ++ii) di[ii] = g_diag[b * DIM + gib + ii];
#pragma unroll
    for (int jj = 0; jj < 8; ++jj) dj[jj] = g_diag[b * DIM + gjb + 16 * jj];

    float* outb = out + (size_t)b * TRIU_PER_B;
    float rpart[8], cpart[8];
#pragma unroll
    for (int i = 0; i < 8; ++i) { rpart[i] = 0.f; cpart[i] = 0.f; }

#pragma unroll
    for (int ii = 0; ii < 8; ++ii) {
        int gi = gib + ii;
        int rowbase = gi * DIM - (gi * (gi - 1)) / 2 - gi;  // pos = rowbase + j
#pragma unroll
        for (int jj = 0; jj < 8; ++jj) {
            int gj = gjb + 16 * jj;
            float g  = acc[ii][jj] * INV2M;
            float dc = fmaxf(di[ii] + dj[jj] - 2.0f * g, 0.0f) + EPS_C;
            float v  = exp2f(ALPHA_C * __log2f(dc));
            if (gj >= gi) {
                outb[rowbase + gj] = v;
                rpart[ii] += v;
                cpart[jj] += (gj > gi) ? v : 0.f;
            }
        }
    }

    // row partials: reduce across the 16 tx-lanes that share ty
#pragma unroll
    for (int o = 1; o < 16; o <<= 1)
#pragma unroll
        for (int ii = 0; ii < 8; ++ii)
            rpart[ii] += __shfl_xor_sync(0xffffffffu, rpart[ii], o);
    if (tx == 0) {
#pragma unroll
        for (int ii = 0; ii < 8; ++ii)
            atomicAdd(&g_rowsum[b * DIM + gib + ii], rpart[ii]);
    }

    // col partials: combine the 2 ty's within each warp, then smem, then global
#pragma unroll
    for (int jj = 0; jj < 8; ++jj)
        cpart[jj] += __shfl_xor_sync(0xffffffffu, cpart[jj], 16);
    if ((tid & 16) == 0) {
#pragma unroll
        for (int jj = 0; jj < 8; ++jj)
            atomicAdd(&cAcc[tx + 16 * jj], cpart[jj]);
    }
    __syncthreads();
    if (tid < 128)
        atomicAdd(&g_rowsum[b * DIM + tj * 128 + tid], cAcc[tid]);
}

// ---------------------------------------------------------------------------
// Kernel 3: finalize per-batch means (rmean = rowsum/dim, tot = sum/dim^2)
// ---------------------------------------------------------------------------
__global__ void k_means() {
    int b   = blockIdx.x;
    int tid = threadIdx.x;
    __shared__ float red[256];
    float s = 0.f;
    for (int i = tid; i < DIM; i += 256) {
        float rs = g_rowsum[b * DIM + i];
        g_rmean[b * DIM + i] = rs * (1.0f / DIM);
        s += rs;
    }
    red[tid] = s;
    __syncthreads();
    for (int o = 128; o; o >>= 1) {
        if (tid < o) red[tid] += red[tid + o];
        __syncthreads();
    }
    if (tid == 0) g_tot[b] = red[0] * (1.0f / ((float)DIM * (float)DIM));
}

// ---------------------------------------------------------------------------
// Kernel 4: in-place double-centering over the triu-packed output.
// block = one (batch, row i); elements j = i..1023 are contiguous in out.
// ---------------------------------------------------------------------------
__global__ void k_center(float* __restrict__ out) {
    int i = blockIdx.x;
    int b = blockIdx.y;
    int len = DIM - i;
    float ri = g_rmean[b * DIM + i];
    float tt = g_tot[b];
    int rowbase = i * DIM - (i * (i - 1)) / 2;  // pos of (i, j=i)
    float* p = out + (size_t)b * TRIU_PER_B + rowbase;
    const float* rm = &g_rmean[b * DIM + i];
    for (int k = threadIdx.x; k < len; k += blockDim.x) {
        p[k] = p[k] - ri - rm[k] + tt;
    }
}

// ---------------------------------------------------------------------------
extern "C" void kernel_launch(void* const* d_in, const int* in_sizes, int n_in,
                              void* d_out, int out_size) {
    (void)in_sizes; (void)n_in; (void)out_size;
    const float* x = (const float*)d_in[0];
    float* out = (float*)d_out;

    k_diag<<<(BATCH * DIM) / 8, 256>>>(x);
    k_main<<<BATCH * NTRI, 256>>>(x, out);
    k_means<<<BATCH, 256>>>();
    k_center<<<dim3(DIM, BATCH), 256>>>(out);
}

// round 4
// speedup vs baseline: 1.6647x; 1.6647x over previous
#include <cuda_runtime.h>
#include <cuda_bf16.h>
#include <cstdint>

#define BATCH 32
#define DIM 1024
#define MLEN 512
#define NTILE 8                /* DIM / 128 */
#define NTRI 36                /* triu tile count */
#define TRIU_PER_B 524800      /* 1024*1025/2 */
#define INV2M (1.0f / 1024.0f)
#define ALPHA_C 0.4f
#define EPS_C 1e-5f
#define DIAG_V 0.01f           /* (1e-5)^0.4 exactly (fp32) */

#define STR 40                 /* smem row stride in bf16 elems (conflict-free) */
#define TILE_ELEMS (128 * STR) /* 5120 */
#define STAGE_ELEMS (4 * TILE_ELEMS)
#define SMEM_MAIN (2 * STAGE_ELEMS * 2)  /* bytes: 81920 */

// ---- scratch (no device allocation allowed) -------------------------------
__device__ __nv_bfloat16 g_hi[(size_t)BATCH * DIM * MLEN];
__device__ __nv_bfloat16 g_lo[(size_t)BATCH * DIM * MLEN];
__device__ float g_diag[BATCH * DIM];
__device__ float g_rowsum[BATCH * DIM];
__device__ float g_rmean[BATCH * DIM];
__device__ float g_tot[BATCH];

#define MMA_BF16(D, A, B)                                                      \
    asm volatile(                                                              \
        "mma.sync.aligned.m16n8k16.row.col.f32.bf16.bf16.f32 "                 \
        "{%0,%1,%2,%3},{%4,%5,%6,%7},{%8,%9},{%0,%1,%2,%3};"                   \
        : "+f"((D)[0]), "+f"((D)[1]), "+f"((D)[2]), "+f"((D)[3])               \
        : "r"((A)[0]), "r"((A)[1]), "r"((A)[2]), "r"((A)[3]),                  \
          "r"((B)[0]), "r"((B)[1]))

// ---------------------------------------------------------------------------
// Kernel 1: split fp32 -> bf16 hi/lo, fused diag + rowsum zero. 1 warp/row.
// ---------------------------------------------------------------------------
__global__ void k_split(const float* __restrict__ x) {
    int row  = blockIdx.x * 8 + (threadIdx.x >> 5);
    int lane = threadIdx.x & 31;
    const float4* p = (const float4*)(x + (size_t)row * MLEN);
    __nv_bfloat16* ph = g_hi + (size_t)row * MLEN;
    __nv_bfloat16* pl = g_lo + (size_t)row * MLEN;
    float s = 0.f;
#pragma unroll
    for (int it = 0; it < 4; ++it) {
        int idx = lane + 32 * it;
        float4 v = p[idx];
        s += v.x * v.x + v.y * v.y + v.z * v.z + v.w * v.w;
        __nv_bfloat16 hh[4], ll[4];
        float e[4] = {v.x, v.y, v.z, v.w};
#pragma unroll
        for (int k = 0; k < 4; ++k) {
            hh[k] = __float2bfloat16(e[k]);
            ll[k] = __float2bfloat16(e[k] - __bfloat162float(hh[k]));
        }
        *(uint2*)(ph + idx * 4) = *(uint2*)hh;
        *(uint2*)(pl + idx * 4) = *(uint2*)ll;
    }
#pragma unroll
    for (int o = 16; o; o >>= 1) s += __shfl_xor_sync(0xffffffffu, s, o);
    if (lane == 0) {
        g_diag[row]   = s * INV2M;
        g_rowsum[row] = 0.f;
    }
}

// ---------------------------------------------------------------------------
// Kernel 2: HMMA (mma.sync bf16 x3) triu-tiled Gram + dcov + pow + store.
// 128x128 tile, 8 warps (2x4), warp tile 64x32, K chunks of 32, double buffer.
// ---------------------------------------------------------------------------
__global__ void __launch_bounds__(256, 1) k_main(float* __restrict__ out) {
    extern __shared__ __nv_bfloat16 S[];
    __shared__ float rAcc[128], cAcc[128];

    int tid = threadIdx.x, wid = tid >> 5, lane = tid & 31;
    int g   = lane >> 2, tg = lane & 3;
    int wm  = wid >> 2, wn = wid & 3;

    int blk = blockIdx.x;
    int b = blk / NTRI;
    int t = blk - b * NTRI;
    int ti = 0;
    while (t >= NTILE - ti) { t -= NTILE - ti; ++ti; }
    int tj = ti + t;

    if (tid < 128) { rAcc[tid] = 0.f; cAcc[tid] = 0.f; }

    size_t rowA = ((size_t)b * DIM + (size_t)ti * 128) * MLEN;
    size_t rowB = ((size_t)b * DIM + (size_t)tj * 128) * MLEN;
    const __nv_bfloat16* srcs[4] = {g_hi + rowA, g_lo + rowA,
                                    g_hi + rowB, g_lo + rowB};

    float acc[4][4][4];
#pragma unroll
    for (int i = 0; i < 4; ++i)
#pragma unroll
        for (int j = 0; j < 4; ++j)
#pragma unroll
            for (int k = 0; k < 4; ++k) acc[i][j][k] = 0.f;

    uint4 pf[8];
    // prefetch chunk 0
#pragma unroll
    for (int tt = 0; tt < 4; ++tt)
#pragma unroll
        for (int it = 0; it < 2; ++it) {
            int v = tid + 256 * it;
            int row = v >> 2, seg = v & 3;
            pf[tt * 2 + it] = *(const uint4*)(srcs[tt] + (size_t)row * MLEN + seg * 8);
        }
    // store chunk 0 into stage 0
#pragma unroll
    for (int tt = 0; tt < 4; ++tt)
#pragma unroll
        for (int it = 0; it < 2; ++it) {
            int v = tid + 256 * it;
            int row = v >> 2, seg = v & 3;
            *(uint4*)(S + tt * TILE_ELEMS + row * STR + seg * 8) = pf[tt * 2 + it];
        }
    __syncthreads();

#pragma unroll 1
    for (int kc = 0; kc < 16; ++kc) {
        int st = kc & 1;
        if (kc + 1 < 16) {
#pragma unroll
            for (int tt = 0; tt < 4; ++tt)
#pragma unroll
                for (int it = 0; it < 2; ++it) {
                    int v = tid + 256 * it;
                    int row = v >> 2, seg = v & 3;
                    pf[tt * 2 + it] = *(const uint4*)(srcs[tt] + (size_t)row * MLEN +
                                                      (kc + 1) * 32 + seg * 8);
                }
        }
        const __nv_bfloat16* SAh = S + st * STAGE_ELEMS;
        const __nv_bfloat16* SAl = SAh + TILE_ELEMS;
        const __nv_bfloat16* SBh = SAl + TILE_ELEMS;
        const __nv_bfloat16* SBl = SBh + TILE_ELEMS;

#pragma unroll
        for (int ks = 0; ks < 2; ++ks) {
            int ck = ks * 16 + tg * 2;
            uint32_t bh[4][2], bl[4][2];
#pragma unroll
            for (int nt = 0; nt < 4; ++nt) {
                int jr = wn * 32 + nt * 8 + g;
                bh[nt][0] = *(const uint32_t*)(SBh + jr * STR + ck);
                bh[nt][1] = *(const uint32_t*)(SBh + jr * STR + ck + 8);
                bl[nt][0] = *(const uint32_t*)(SBl + jr * STR + ck);
                bl[nt][1] = *(const uint32_t*)(SBl + jr * STR + ck + 8);
            }
#pragma unroll
            for (int mt = 0; mt < 4; ++mt) {
                int r0 = wm * 64 + mt * 16 + g;
                uint32_t ah[4], al[4];
                ah[0] = *(const uint32_t*)(SAh + r0 * STR + ck);
                ah[1] = *(const uint32_t*)(SAh + (r0 + 8) * STR + ck);
                ah[2] = *(const uint32_t*)(SAh + r0 * STR + ck + 8);
                ah[3] = *(const uint32_t*)(SAh + (r0 + 8) * STR + ck + 8);
                al[0] = *(const uint32_t*)(SAl + r0 * STR + ck);
                al[1] = *(const uint32_t*)(SAl + (r0 + 8) * STR + ck);
                al[2] = *(const uint32_t*)(SAl + r0 * STR + ck + 8);
                al[3] = *(const uint32_t*)(SAl + (r0 + 8) * STR + ck + 8);
#pragma unroll
                for (int nt = 0; nt < 4; ++nt) {
                    MMA_BF16(acc[mt][nt], ah, bh[nt]);
                    MMA_BF16(acc[mt][nt], ah, bl[nt]);
                    MMA_BF16(acc[mt][nt], al, bh[nt]);
                }
            }
        }
        __syncthreads();   // everyone done reading stage st
        if (kc + 1 < 16) {
            int os = st ^ 1;
#pragma unroll
            for (int tt = 0; tt < 4; ++tt)
#pragma unroll
                for (int it = 0; it < 2; ++it) {
                    int v = tid + 256 * it;
                    int row = v >> 2, seg = v & 3;
                    *(uint4*)(S + os * STAGE_ELEMS + tt * TILE_ELEMS + row * STR + seg * 8) =
                        pf[tt * 2 + it];
                }
            __syncthreads();
        }
    }

    // ---- epilogue ----------------------------------------------------------
    float diA[8], djB[8];
#pragma unroll
    for (int mt = 0; mt < 4; ++mt) {
        diA[mt * 2 + 0] = g_diag[b * DIM + ti * 128 + wm * 64 + mt * 16 + g];
        diA[mt * 2 + 1] = g_diag[b * DIM + ti * 128 + wm * 64 + mt * 16 + g + 8];
    }
#pragma unroll
    for (int nt = 0; nt < 4; ++nt) {
        djB[nt * 2 + 0] = g_diag[b * DIM + tj * 128 + wn * 32 + nt * 8 + tg * 2];
        djB[nt * 2 + 1] = g_diag[b * DIM + tj * 128 + wn * 32 + nt * 8 + tg * 2 + 1];
    }

    float* V = (float*)S;  // reuse stages: 128 x 132 floats
    float r8[8], c8[8];
#pragma unroll
    for (int k = 0; k < 8; ++k) { r8[k] = 0.f; c8[k] = 0.f; }

#pragma unroll
    for (int mt = 0; mt < 4; ++mt)
#pragma unroll
        for (int nt = 0; nt < 4; ++nt)
#pragma unroll
            for (int e = 0; e < 4; ++e) {
                int pair = e >> 1, cbit = e & 1;
                int il = wm * 64 + mt * 16 + g + pair * 8;
                int jl = wn * 32 + nt * 8 + tg * 2 + cbit;
                int gi = ti * 128 + il;
                int gj = tj * 128 + jl;
                float gv = acc[mt][nt][pair * 2 + cbit] * INV2M;
                float dc = fmaxf(diA[mt * 2 + pair] + djB[nt * 2 + cbit] - 2.0f * gv,
                                 0.0f) + EPS_C;
                float v = exp2f(ALPHA_C * __log2f(dc));
                // exact diagonal: reference has dcov_ii == 0 -> (eps)^alpha
                if (gi == gj) v = DIAG_V;
                V[il * 132 + jl] = v;
                r8[mt * 2 + pair] += (gj >= gi) ? v : 0.f;
                c8[nt * 2 + cbit] += (gj > gi) ? v : 0.f;
            }

    // row partials: reduce over tg (lane bits 0,1)
#pragma unroll
    for (int k = 0; k < 8; ++k) {
        r8[k] += __shfl_xor_sync(0xffffffffu, r8[k], 1);
        r8[k] += __shfl_xor_sync(0xffffffffu, r8[k], 2);
    }
    if (tg == 0) {
#pragma unroll
        for (int k = 0; k < 8; ++k)
            atomicAdd(&rAcc[wm * 64 + (k >> 1) * 16 + g + (k & 1) * 8], r8[k]);
    }
    // col partials: reduce over g (lane bits 2,3,4)
#pragma unroll
    for (int k = 0; k < 8; ++k) {
        c8[k] += __shfl_xor_sync(0xffffffffu, c8[k], 4);
        c8[k] += __shfl_xor_sync(0xffffffffu, c8[k], 8);
        c8[k] += __shfl_xor_sync(0xffffffffu, c8[k], 16);
    }
    if (g == 0) {
#pragma unroll
        for (int k = 0; k < 8; ++k)
            atomicAdd(&cAcc[wn * 32 + (k >> 1) * 8 + tg * 2 + (k & 1)], c8[k]);
    }
    __syncthreads();

    if (tid < 128) {
        atomicAdd(&g_rowsum[b * DIM + ti * 128 + tid], rAcc[tid]);
        atomicAdd(&g_rowsum[b * DIM + tj * 128 + tid], cAcc[tid]);
    }

    float* outb = out + (size_t)b * TRIU_PER_B;
#pragma unroll 1
    for (int rr = 0; rr < 16; ++rr) {
        int il  = wid * 16 + rr;
        int gri = ti * 128 + il;
        int rbp = gri * DIM - (gri * (gri - 1)) / 2 - gri;
#pragma unroll
        for (int k = 0; k < 4; ++k) {
            int j  = lane + 32 * k;
            int gj = tj * 128 + j;
            if (gj >= gri) outb[rbp + gj] = V[il * 132 + j];
        }
    }
}

// ---------------------------------------------------------------------------
// Kernel 3: finalize per-batch means
// ---------------------------------------------------------------------------
__global__ void k_means() {
    int b = blockIdx.x, tid = threadIdx.x;
    __shared__ float red[256];
    float s = 0.f;
    for (int i = tid; i < DIM; i += 256) {
        float rs = g_rowsum[b * DIM + i];
        g_rmean[b * DIM + i] = rs * (1.0f / DIM);
        s += rs;
    }
    red[tid] = s;
    __syncthreads();
    for (int o = 128; o; o >>= 1) {
        if (tid < o) red[tid] += red[tid + o];
        __syncthreads();
    }
    if (tid == 0) g_tot[b] = red[0] * (1.0f / ((float)DIM * (float)DIM));
}

// ---------------------------------------------------------------------------
// Kernel 4: flat float4 double-centering with sqrt-based row inversion.
// ---------------------------------------------------------------------------
__device__ __forceinline__ int rb_of(int i) { return (i * (2 * DIM + 1 - i)) >> 1; }

__global__ void k_center(float* __restrict__ out) {
    int idx = blockIdx.x * blockDim.x + threadIdx.x;   // float4 index
    int b  = idx / (TRIU_PER_B / 4);
    int p  = (idx - b * (TRIU_PER_B / 4)) * 4;
    float arg = (float)(4198401 - 8 * p);
    int i = (int)((2049.0f - sqrtf(arg)) * 0.5f);
    if (i < 0) i = 0;
    if (i > DIM - 1) i = DIM - 1;
    while (i > 0 && rb_of(i) > p) --i;
    while (rb_of(i + 1) <= p) ++i;

    const float* rm = g_rmean + b * DIM;
    float tt = g_tot[b];
    float* ptr = out + (size_t)b * TRIU_PER_B + p;
    float4 v = *(float4*)ptr;
    float e[4] = {v.x, v.y, v.z, v.w};
    int ii = i;
#pragma unroll
    for (int k = 0; k < 4; ++k) {
        while (rb_of(ii + 1) <= p + k) ++ii;
        int j = p + k - rb_of(ii) + ii;
        e[k] = e[k] - rm[ii] - rm[j] + tt;
    }
    v.x = e[0]; v.y = e[1]; v.z = e[2]; v.w = e[3];
    *(float4*)ptr = v;
}

// ---------------------------------------------------------------------------
extern "C" void kernel_launch(void* const* d_in, const int* in_sizes, int n_in,
                              void* d_out, int out_size) {
    (void)in_sizes; (void)n_in; (void)out_size;
    const float* x = (const float*)d_in[0];
    float* out = (float*)d_out;

    cudaFuncSetAttribute(k_main, cudaFuncAttributeMaxDynamicSharedMemorySize,
                         SMEM_MAIN);

    k_split<<<(BATCH * DIM) / 8, 256>>>(x);
    k_main<<<BATCH * NTRI, 256, SMEM_MAIN>>>(out);
    k_means<<<BATCH, 256>>>();
    k_center<<<(BATCH * TRIU_PER_B / 4) / 256, 256>>>(out);
}